// round 5
// baseline (speedup 1.0000x reference)
#include <cuda_runtime.h>
#include <cstdint>

// Problem constants
#define B_ 128
#define T_ 100
#define I_ 1024
#define O_ 1024
#define EPSV 1e-8f

// Scratch (static __device__ arrays — allocation-free per harness rules)
__device__ float g_h[(size_t)B_ * T_ * O_];    // 52.4 MB: h = x@w, [B,T,O]
__device__ float g_d[(size_t)O_ * O_];         // 4 MB:  d = w^T w
__device__ float g_inv[O_];                    // 1/(norm+eps)
__device__ int   g_cnt[T_];                    // per-step spike counts

// ---------------------------------------------------------------------------
// helpers (plain sm_80-class PTX only — harness targets sm_103 w/o 'a':
// no tcgen05/TMEM; tensor path is mma.sync tf32)
// ---------------------------------------------------------------------------
__device__ __forceinline__ float tf32r(float x) {
    uint32_t r;
    asm("cvt.rna.tf32.f32 %0, %1;" : "=r"(r) : "f"(x));
    return __uint_as_float(r);
}

__device__ __forceinline__ void mma_tf32(float c[4],
                                         float a0, float a1, float a2, float a3,
                                         float b0, float b1) {
    asm volatile(
        "mma.sync.aligned.m16n8k8.row.col.f32.tf32.tf32.f32 "
        "{%0,%1,%2,%3}, {%4,%5,%6,%7}, {%8,%9}, {%0,%1,%2,%3};"
        : "+f"(c[0]), "+f"(c[1]), "+f"(c[2]), "+f"(c[3])
        : "r"(__float_as_uint(a0)), "r"(__float_as_uint(a1)),
          "r"(__float_as_uint(a2)), "r"(__float_as_uint(a3)),
          "r"(__float_as_uint(b0)), "r"(__float_as_uint(b1)));
}

// ---------------------------------------------------------------------------
// gemm_h_mma: g_h[M,N] = x[M,K] * w[K,N], M=12800, N=K=1024.
// 3xTF32 (hi*hi + hi*lo + lo*hi). CTA 128x128, 8 warps (2m x 4n), BK=16.
// SMEM holds tiles in MMA-FRAGMENT ORDER so consumer loads are LDS.128/LDS.64:
//   A frag addr: ((ktile*8 + mt)*32 + lane)*4 + j   (j = (r>=8) + 2*(kk>=4))
//   B frag addr: ((ktile*16 + nt)*32 + lane)*2 + j  (j = kk>=4)
// hi and lo blocks are separate; 32 KB per stage, double-buffered (64 KB).
// ---------------------------------------------------------------------------
#define OFF2_AH 0
#define OFF2_AL 2048
#define OFF2_BH 4096
#define OFF2_BL 6144
#define STG2    8192                      // floats per stage
#define GH_SMEM_BYTES (2 * STG2 * 4)      // 65536 B

__global__ void __launch_bounds__(256) gemm_h_mma(
    const float* __restrict__ X, const float* __restrict__ W)
{
    extern __shared__ float sm[];
    const int tid  = threadIdx.x;
    const int wid  = tid >> 5;
    const int lane = tid & 31;
    const int g    = lane >> 2;
    const int t4   = lane & 3;
    const int bm   = blockIdx.y * 128;
    const int bn   = blockIdx.x * 128;
    const int wmt0 = (wid >> 2) * 4;    // warp's first m-tile (of 8)
    const int wnt0 = (wid & 3) * 4;     // warp's first n-tile (of 16)

    // producer assignments
    const int am     = tid >> 1;        // A row 0..127
    const int aktile = tid & 1;         // A ktile 0/1 (k sub-offset 0 or 8)

    float acc[4][4][4];
#pragma unroll
    for (int i = 0; i < 4; i++)
#pragma unroll
        for (int j = 0; j < 4; j++)
#pragma unroll
            for (int q = 0; q < 4; q++) acc[i][j][q] = 0.f;

    float4 aR[2], bR[2];

    auto gload = [&](int k0) {
        const float* ap = X + (size_t)(bm + am) * I_ + k0 + aktile * 8;
        aR[0] = *(const float4*)(ap);
        aR[1] = *(const float4*)(ap + 4);
#pragma unroll
        for (int q = 0; q < 2; q++) {
            int idx = tid + q * 256;          // 0..511 float4s of 16x128 B tile
            int r = idx >> 5, c = (idx & 31) * 4;
            bR[q] = *(const float4*)&W[(size_t)(k0 + r) * O_ + bn + c];
        }
    };

    auto sstore = [&](int s) {
        float* base = sm + s * STG2;
        // ---- A: row am, ktile aktile, kk = 0..7 ----
        {
            const int mt = am >> 4;
            const int r  = am & 15;
            const int gg = r & 7;
            const int j0 = r >> 3;
            float* AH = base + OFF2_AH + ((aktile * 8 + mt) * 32 + gg * 4) * 4 + j0;
            float* AL = base + OFF2_AL + ((aktile * 8 + mt) * 32 + gg * 4) * 4 + j0;
            float v[8] = {aR[0].x, aR[0].y, aR[0].z, aR[0].w,
                          aR[1].x, aR[1].y, aR[1].z, aR[1].w};
#pragma unroll
            for (int kk = 0; kk < 8; kk++) {
                float hi = tf32r(v[kk]);
                float lo = tf32r(v[kk] - hi);
                const int off = (kk & 3) * 4 + (kk >> 2) * 2;
                AH[off] = hi;
                AL[off] = lo;
            }
        }
        // ---- B: two float4s, each = (k=r, n=c..c+3) ----
#pragma unroll
        for (int q = 0; q < 2; q++) {
            int idx = tid + q * 256;
            int r = idx >> 5, c = (idx & 31) * 4;
            const int ktile = r >> 3, kk = r & 7;
            const int tt4 = kk & 3, j = kk >> 2;
            const int nt = c >> 3, cg = c & 7;
            float* BH = base + OFF2_BH + ((ktile * 16 + nt) * 32 + tt4) * 2 + j + cg * 8;
            float* BL = base + OFF2_BL + ((ktile * 16 + nt) * 32 + tt4) * 2 + j + cg * 8;
            float v[4] = {bR[q].x, bR[q].y, bR[q].z, bR[q].w};
#pragma unroll
            for (int i = 0; i < 4; i++) {
                float hi = tf32r(v[i]);
                float lo = tf32r(v[i] - hi);
                BH[i * 8] = hi;
                BL[i * 8] = lo;
            }
        }
    };

    auto compute = [&](int s) {
        const float* base = sm + s * STG2;
#pragma unroll
        for (int ktile = 0; ktile < 2; ktile++) {
            const float* afh = base + OFF2_AH + ((ktile * 8 + wmt0) * 32 + lane) * 4;
            const float* afl = base + OFF2_AL + ((ktile * 8 + wmt0) * 32 + lane) * 4;
            const float* bfh = base + OFF2_BH + ((ktile * 16 + wnt0) * 32 + lane) * 2;
            const float* bfl = base + OFF2_BL + ((ktile * 16 + wnt0) * 32 + lane) * 2;
            float4 ah[4], al[4];
            float2 bh[4], bl[4];
#pragma unroll
            for (int mt = 0; mt < 4; mt++) {
                ah[mt] = *(const float4*)(afh + mt * 128);
                al[mt] = *(const float4*)(afl + mt * 128);
            }
#pragma unroll
            for (int nt = 0; nt < 4; nt++) {
                bh[nt] = *(const float2*)(bfh + nt * 64);
                bl[nt] = *(const float2*)(bfl + nt * 64);
            }
#pragma unroll
            for (int mt = 0; mt < 4; mt++)
#pragma unroll
                for (int nt = 0; nt < 4; nt++) {
                    mma_tf32(acc[mt][nt], ah[mt].x, ah[mt].y, ah[mt].z, ah[mt].w,
                             bh[nt].x, bh[nt].y);
                    mma_tf32(acc[mt][nt], ah[mt].x, ah[mt].y, ah[mt].z, ah[mt].w,
                             bl[nt].x, bl[nt].y);
                    mma_tf32(acc[mt][nt], al[mt].x, al[mt].y, al[mt].z, al[mt].w,
                             bh[nt].x, bh[nt].y);
                }
        }
    };

    gload(0);
    sstore(0);
    __syncthreads();

    for (int kt = 0; kt < 64; kt++) {
        if (kt < 63) gload((kt + 1) * 16);
        compute(kt & 1);
        if (kt < 63) sstore((kt + 1) & 1);
        __syncthreads();
    }

    // epilogue: c frag -> g_h (float2 per pair of columns)
#pragma unroll
    for (int mt = 0; mt < 4; mt++)
#pragma unroll
        for (int nt = 0; nt < 4; nt++) {
            const int row0 = bm + (wmt0 + mt) * 16 + g;
            const int col  = bn + (wnt0 + nt) * 8 + t4 * 2;
            *(float2*)&g_h[(size_t)row0 * O_ + col] =
                make_float2(acc[mt][nt][0], acc[mt][nt][1]);
            *(float2*)&g_h[(size_t)(row0 + 8) * O_ + col] =
                make_float2(acc[mt][nt][2], acc[mt][nt][3]);
        }
}

// ---------------------------------------------------------------------------
// GEMM 2 (SIMT): g_d[i,o] = sum_a w[a,i]*w[a,o]  (A^T A, A = w [1024,1024])
// ---------------------------------------------------------------------------
__global__ __launch_bounds__(256, 2) void gemm_d(const float* __restrict__ W)
{
    __shared__ float As[8][128];
    __shared__ float Bs[8][132];

    const int tid = threadIdx.x;
    const int bm = blockIdx.y * 128;
    const int bn = blockIdx.x * 128;
    const int K = I_, N = O_;

    const int brow = tid >> 5;
    const int bcol = (tid & 31) * 4;
    const int tr   = (tid >> 4) * 8;
    const int tc   = (tid & 15) * 8;

    float acc[8][8];
#pragma unroll
    for (int i = 0; i < 8; i++)
#pragma unroll
        for (int j = 0; j < 8; j++) acc[i][j] = 0.f;

    for (int k0 = 0; k0 < K; k0 += 8) {
        float4 a4 = *(const float4*)&W[(size_t)(k0 + brow) * N + bm + bcol];
        float4 b4 = *(const float4*)&W[(size_t)(k0 + brow) * N + bn + bcol];
        __syncthreads();
        *(float4*)&As[brow][bcol & 127] = a4;
        *(float4*)&Bs[brow][bcol] = b4;
        __syncthreads();
#pragma unroll
        for (int kk = 0; kk < 8; kk++) {
            float ar[8], br[8];
#pragma unroll
            for (int i = 0; i < 8; i++) ar[i] = As[kk][tr + i];
#pragma unroll
            for (int j = 0; j < 8; j++) br[j] = Bs[kk][tc + j];
#pragma unroll
            for (int i = 0; i < 8; i++)
#pragma unroll
                for (int j = 0; j < 8; j++) acc[i][j] += ar[i] * br[j];
        }
    }

#pragma unroll
    for (int i = 0; i < 8; i++)
#pragma unroll
        for (int j = 0; j < 8; j += 4) {
            float4 o4 = make_float4(acc[i][j], acc[i][j + 1], acc[i][j + 2], acc[i][j + 3]);
            *(float4*)&g_d[(size_t)(bm + tr + i) * N + bn + tc + j] = o4;
        }
}

// ---------------------------------------------------------------------------
// prep: inv_norm from diag(d), zero per-step counters
// ---------------------------------------------------------------------------
__global__ void prep_kernel()
{
    int idx = blockIdx.x * blockDim.x + threadIdx.x;
    if (idx < O_) g_inv[idx] = 1.0f / (g_d[(size_t)idx * O_ + idx] + EPSV);
    if (idx < T_) g_cnt[idx] = 0;
}

// ---------------------------------------------------------------------------
// Scan v2: one CTA per batch, 1024 threads, one neuron per thread.
// mem in a register; spike list double-buffered; h prefetched one step ahead.
// Sparse-exact: rst/rec sum only active rows of d / V (adding 0.0 is exact).
// ---------------------------------------------------------------------------
__global__ void __launch_bounds__(1024) scan_kernel(
    const float* __restrict__ V,
    const float* __restrict__ bb,
    const float* __restrict__ beta_p,
    float* __restrict__ out)
{
    const int b = blockIdx.x;
    const int o = threadIdx.x;          // neuron index, 0..1023
    const float beta = beta_p[0];
    const float ombeta = 1.0f - beta;

    __shared__ int act[2][O_];
    __shared__ int nact[2];
    __shared__ int scnt;

    if (o < 2) nact[o] = 0;
    if (o == 0) scnt = 0;

    float mem = 0.f;
    const float inv = g_inv[o];
    const float bo  = bb[o];
    const float* hrow = g_h + (size_t)b * T_ * O_ + o;
    float*       orow = out + (size_t)b * T_ * O_ + o;

    float h_next = hrow[0];
    __syncthreads();

    int cur = 0;
    for (int t = 0; t < T_; t++) {
        const float h_cur = h_next;
        if (t + 1 < T_) h_next = hrow[(size_t)(t + 1) * O_];   // prefetch

        const int na = nact[cur];
        float rst = 0.f, rec = 0.f;
        for (int a = 0; a < na; a++) {
            const int i = act[cur][a];
            rst += g_d[(size_t)i * O_ + o];
            rec += V[(size_t)i * O_ + o];
        }

        mem = (mem - rst) * beta + (h_cur + rec) * ombeta;
        const float mthr = mem * inv - bo;
        const float s = (mthr > 0.f) ? 1.0f : 0.0f;
        orow[(size_t)t * O_] = s;
        if (s != 0.f) {
            const int p = atomicAdd(&nact[cur ^ 1], 1);
            act[cur ^ 1][p] = o;
            atomicAdd(&scnt, 1);
        }
        __syncthreads();
        if (o == 0) {
            if (scnt) { atomicAdd(&g_cnt[t], scnt); scnt = 0; }
            nact[cur] = 0;
        }
        cur ^= 1;
        __syncthreads();
    }
}

// ---------------------------------------------------------------------------
// finalize: loss and spike-spread scalars
// ---------------------------------------------------------------------------
__global__ void finalize_kernel(float* __restrict__ out, int out_size)
{
    __shared__ int s_tot[128];
    __shared__ int s_max[128];
    const int tid = threadIdx.x;
    int tot = 0, mx = 0;
    for (int t = tid; t < T_; t += 128) {
        int c = g_cnt[t];
        tot += c;
        mx = (c > mx) ? c : mx;
    }
    s_tot[tid] = tot; s_max[tid] = mx;
    __syncthreads();
    for (int s = 64; s > 0; s >>= 1) {
        if (tid < s) {
            s_tot[tid] += s_tot[tid + s];
            s_max[tid] = (s_max[tid + s] > s_max[tid]) ? s_max[tid + s] : s_max[tid];
        }
        __syncthreads();
    }
    if (tid == 0) {
        const size_t base = (size_t)B_ * T_ * O_;
        if ((size_t)out_size >= base + 2) {
            out[base]     = 0.5f * (float)s_tot[0] / (float)((size_t)B_ * T_ * O_);
            out[base + 1] = (float)s_max[0] / (float)(B_ * O_);
        }
    }
}

// ---------------------------------------------------------------------------
extern "C" void kernel_launch(void* const* d_in, const int* in_sizes, int n_in,
                              void* d_out, int out_size)
{
    const float* x    = (const float*)d_in[0];   // [B,T,I]
    const float* w    = (const float*)d_in[1];   // [I,O]
    const float* v    = (const float*)d_in[2];   // [O,O]
    const float* beta = (const float*)d_in[3];   // [1]
    const float* bb   = (const float*)d_in[4];   // [O]
    float* out = (float*)d_out;

    cudaFuncSetAttribute(gemm_h_mma, cudaFuncAttributeMaxDynamicSharedMemorySize,
                         GH_SMEM_BYTES);

    // 1) h = x @ w via mma.sync tf32 (3xTF32), fragment-packed smem
    gemm_h_mma<<<dim3(O_ / 128, (B_ * T_) / 128), 256, GH_SMEM_BYTES>>>(x, w);

    // 2) d = w^T w (SIMT)
    gemm_d<<<dim3(O_ / 128, O_ / 128), 256>>>(w);

    // 3) inv_norm + zero counters
    prep_kernel<<<4, 256>>>();

    // 4) per-batch recurrent scan
    scan_kernel<<<B_, 1024>>>(v, bb, beta, out);

    // 5) scalar losses
    finalize_kernel<<<1, 128>>>(out, out_size);
}

// round 9
// speedup vs baseline: 2.1741x; 2.1741x over previous
#include <cuda_runtime.h>
#include <cstdint>

// Problem constants
#define B_ 128
#define T_ 100
#define I_ 1024
#define O_ 1024
#define EPSV 1e-8f

// Scratch (static __device__ arrays — allocation-free per harness rules).
// NOTE: these are referenced ONLY inside device code (passing a __device__
// symbol as a host-side kernel argument silently passes garbage — R6 bug).
__device__ __align__(16) float g_h[(size_t)B_ * T_ * O_];    // h = x@w, [B,T,O]
__device__ __align__(16) float g_d[(size_t)O_ * O_];         // d = w^T w
__device__ __align__(16) float g_inv[O_];                    // 1/(norm+eps)
__device__ int   g_cnt[T_];                                  // per-step spike counts
__device__ __align__(16) float g_xh[(size_t)B_ * T_ * I_];   // x hi (tf32)
__device__ __align__(16) float g_xl[(size_t)B_ * T_ * I_];   // x lo
__device__ __align__(16) float g_wh[(size_t)I_ * O_];        // w hi [K,N]
__device__ __align__(16) float g_wl[(size_t)I_ * O_];        // w lo [K,N]

// ---------------------------------------------------------------------------
// helpers (plain sm_80-class PTX only — harness targets sm_103 w/o 'a')
// ---------------------------------------------------------------------------
__device__ __forceinline__ float tf32r(float x) {
    uint32_t r;
    asm("cvt.rna.tf32.f32 %0, %1;" : "=r"(r) : "f"(x));
    return __uint_as_float(r);
}
__device__ __forceinline__ uint32_t smem_u32(const void* p) {
    uint32_t a;
    asm("{ .reg .u64 t; cvta.to.shared.u64 t, %1; cvt.u32.u64 %0, t; }" : "=r"(a) : "l"(p));
    return a;
}
__device__ __forceinline__ void cp16(uint32_t dst, const float* src) {
    asm volatile("cp.async.cg.shared.global [%0], [%1], 16;" :: "r"(dst), "l"(src));
}
#define CP_COMMIT() asm volatile("cp.async.commit_group;" ::: "memory")
#define CP_WAIT(n)  asm volatile("cp.async.wait_group %0;" :: "n"(n) : "memory")

__device__ __forceinline__ void mma_tf32(float c[4],
                                         float a0, float a1, float a2, float a3,
                                         float b0, float b1) {
    asm volatile(
        "mma.sync.aligned.m16n8k8.row.col.f32.tf32.tf32.f32 "
        "{%0,%1,%2,%3}, {%4,%5,%6,%7}, {%8,%9}, {%0,%1,%2,%3};"
        : "+f"(c[0]), "+f"(c[1]), "+f"(c[2]), "+f"(c[3])
        : "r"(__float_as_uint(a0)), "r"(__float_as_uint(a1)),
          "r"(__float_as_uint(a2)), "r"(__float_as_uint(a3)),
          "r"(__float_as_uint(b0)), "r"(__float_as_uint(b1)));
}

// ---------------------------------------------------------------------------
// split_x_kernel: x -> (g_xh, g_xl); globals named in device code only
// ---------------------------------------------------------------------------
__global__ void split_x_kernel(const float* __restrict__ src)
{
    const int n4 = (B_ * T_ * I_) / 4;
    const float4* s4 = (const float4*)src;
    float4* h4 = (float4*)g_xh;
    float4* l4 = (float4*)g_xl;
    for (int i = blockIdx.x * blockDim.x + threadIdx.x; i < n4;
         i += gridDim.x * blockDim.x) {
        float4 v = s4[i];
        float4 h, l;
        h.x = tf32r(v.x); l.x = tf32r(v.x - h.x);
        h.y = tf32r(v.y); l.y = tf32r(v.y - h.y);
        h.z = tf32r(v.z); l.z = tf32r(v.z - h.z);
        h.w = tf32r(v.w); l.w = tf32r(v.w - h.w);
        h4[i] = h; l4[i] = l;
    }
}

// ---------------------------------------------------------------------------
// split_w_kernel: w -> (g_wh, g_wl)
// ---------------------------------------------------------------------------
__global__ void split_w_kernel(const float* __restrict__ src)
{
    const int n4 = (I_ * O_) / 4;
    const float4* s4 = (const float4*)src;
    float4* h4 = (float4*)g_wh;
    float4* l4 = (float4*)g_wl;
    for (int i = blockIdx.x * blockDim.x + threadIdx.x; i < n4;
         i += gridDim.x * blockDim.x) {
        float4 v = s4[i];
        float4 h, l;
        h.x = tf32r(v.x); l.x = tf32r(v.x - h.x);
        h.y = tf32r(v.y); l.y = tf32r(v.y - h.y);
        h.z = tf32r(v.z); l.z = tf32r(v.z - h.z);
        h.w = tf32r(v.w); l.w = tf32r(v.w - h.w);
        h4[i] = h; l4[i] = l;
    }
}

// ---------------------------------------------------------------------------
// gemm_h_mma: g_h[M,N] = x[M,K]*w[K,N] via mma.sync tf32 (3xTF32), M=12800.
// CTA 128x128, 512 threads, 16 warps (4m x 4n, 32x32 each), BK=16.
// 4-stage cp.async pipeline of pre-split hi/lo tiles.
// Layouts (floats): A[128][20] m-major pad20, B[16][136] k-major pad136.
// ---------------------------------------------------------------------------
#define AH_OFF 0
#define AL_OFF 2560
#define BH_OFF 5120
#define BL_OFF 7296
#define STGF   9472                         // floats per stage (37888 B)
#define GH_SMEM_BYTES (4 * STGF * 4)        // 151552 B

__global__ void __launch_bounds__(512) gemm_h_mma()
{
    extern __shared__ float smf[];
    const uint32_t sbase = smem_u32(smf);
    const int tid  = threadIdx.x;
    const int wid  = tid >> 5;
    const int lane = tid & 31;
    const int g    = lane >> 2;
    const int t4   = lane & 3;
    const int bm   = blockIdx.y * 128;
    const int bn   = blockIdx.x * 128;
    const int wm   = (wid >> 2) * 32;      // warp m offset
    const int wn   = (wid & 3) * 32;       // warp n offset

    // producer assignments (per thread, per stage): 4 cp.async of 16B
    const int arow = tid >> 2;             // 0..127
    const int akc  = (tid & 3) * 4;        // 0,4,8,12
    const int brow = tid >> 5;             // 0..15
    const int bc   = (tid & 31) * 4;       // 0..124

    float acc[2][4][4];
#pragma unroll
    for (int i = 0; i < 2; i++)
#pragma unroll
        for (int j = 0; j < 4; j++)
#pragma unroll
            for (int q = 0; q < 4; q++) acc[i][j][q] = 0.f;

    auto fill = [&](int stage, int chunk) {
        const uint32_t base = sbase + stage * (STGF * 4);
        const int k0 = chunk * 16;
        cp16(base + (AH_OFF + arow * 20 + akc) * 4,
             g_xh + (size_t)(bm + arow) * I_ + k0 + akc);
        cp16(base + (AL_OFF + arow * 20 + akc) * 4,
             g_xl + (size_t)(bm + arow) * I_ + k0 + akc);
        cp16(base + (BH_OFF + brow * 136 + bc) * 4,
             g_wh + (size_t)(k0 + brow) * O_ + bn + bc);
        cp16(base + (BL_OFF + brow * 136 + bc) * 4,
             g_wl + (size_t)(k0 + brow) * O_ + bn + bc);
        CP_COMMIT();
    };

    auto compute = [&](int stage) {
        const float* base = smf + stage * STGF;
        const float* Ah = base + AH_OFF;
        const float* Al = base + AL_OFF;
        const float* Bh = base + BH_OFF;
        const float* Bl = base + BL_OFF;
#pragma unroll
        for (int kt = 0; kt < 2; kt++) {
            const int ks = kt * 8;
            float ah[2][4], al[2][4];
            float bh[4][2], bl[4][2];
#pragma unroll
            for (int mt = 0; mt < 2; mt++) {
                const int r0 = (wm + mt * 16 + g) * 20;
                const int r1 = (wm + mt * 16 + g + 8) * 20;
                ah[mt][0] = Ah[r0 + ks + t4];
                ah[mt][1] = Ah[r1 + ks + t4];
                ah[mt][2] = Ah[r0 + ks + t4 + 4];
                ah[mt][3] = Ah[r1 + ks + t4 + 4];
                al[mt][0] = Al[r0 + ks + t4];
                al[mt][1] = Al[r1 + ks + t4];
                al[mt][2] = Al[r0 + ks + t4 + 4];
                al[mt][3] = Al[r1 + ks + t4 + 4];
            }
#pragma unroll
            for (int nt = 0; nt < 4; nt++) {
                const int cn = wn + nt * 8 + g;
                bh[nt][0] = Bh[(ks + t4) * 136 + cn];
                bh[nt][1] = Bh[(ks + t4 + 4) * 136 + cn];
                bl[nt][0] = Bl[(ks + t4) * 136 + cn];
                bl[nt][1] = Bl[(ks + t4 + 4) * 136 + cn];
            }
#pragma unroll
            for (int mt = 0; mt < 2; mt++)
#pragma unroll
                for (int nt = 0; nt < 4; nt++) {
                    mma_tf32(acc[mt][nt], ah[mt][0], ah[mt][1], ah[mt][2], ah[mt][3],
                             bh[nt][0], bh[nt][1]);
                    mma_tf32(acc[mt][nt], ah[mt][0], ah[mt][1], ah[mt][2], ah[mt][3],
                             bl[nt][0], bl[nt][1]);
                    mma_tf32(acc[mt][nt], al[mt][0], al[mt][1], al[mt][2], al[mt][3],
                             bh[nt][0], bh[nt][1]);
                }
        }
    };

    fill(0, 0);
    fill(1, 1);
    fill(2, 2);

    for (int c = 0; c < 64; c++) {
        CP_WAIT(2);               // chunk c complete (3 groups in flight)
        __syncthreads();
        compute(c & 3);
        if (c + 3 < 64) fill((c + 3) & 3, c + 3);   // slot consumed at iter c-1
        else CP_COMMIT();                           // empty group keeps count
    }

    // epilogue
#pragma unroll
    for (int mt = 0; mt < 2; mt++)
#pragma unroll
        for (int nt = 0; nt < 4; nt++) {
            const int row0 = bm + wm + mt * 16 + g;
            const int col  = bn + wn + nt * 8 + t4 * 2;
            *(float2*)&g_h[(size_t)row0 * O_ + col] =
                make_float2(acc[mt][nt][0], acc[mt][nt][1]);
            *(float2*)&g_h[(size_t)(row0 + 8) * O_ + col] =
                make_float2(acc[mt][nt][2], acc[mt][nt][3]);
        }
}

// ---------------------------------------------------------------------------
// GEMM 2 (SIMT): g_d[i,o] = sum_a w[a,i]*w[a,o]  (A^T A, A = w [1024,1024])
// ---------------------------------------------------------------------------
__global__ __launch_bounds__(256, 2) void gemm_d(const float* __restrict__ W)
{
    __shared__ float As[8][128];
    __shared__ float Bs[8][132];

    const int tid = threadIdx.x;
    const int bm = blockIdx.y * 128;
    const int bn = blockIdx.x * 128;
    const int K = I_, N = O_;

    const int brow = tid >> 5;
    const int bcol = (tid & 31) * 4;
    const int tr   = (tid >> 4) * 8;
    const int tc   = (tid & 15) * 8;

    float acc[8][8];
#pragma unroll
    for (int i = 0; i < 8; i++)
#pragma unroll
        for (int j = 0; j < 8; j++) acc[i][j] = 0.f;

    for (int k0 = 0; k0 < K; k0 += 8) {
        float4 a4 = *(const float4*)&W[(size_t)(k0 + brow) * N + bm + bcol];
        float4 b4 = *(const float4*)&W[(size_t)(k0 + brow) * N + bn + bcol];
        __syncthreads();
        *(float4*)&As[brow][bcol & 127] = a4;
        *(float4*)&Bs[brow][bcol] = b4;
        __syncthreads();
#pragma unroll
        for (int kk = 0; kk < 8; kk++) {
            float ar[8], br[8];
#pragma unroll
            for (int i = 0; i < 8; i++) ar[i] = As[kk][tr + i];
#pragma unroll
            for (int j = 0; j < 8; j++) br[j] = Bs[kk][tc + j];
#pragma unroll
            for (int i = 0; i < 8; i++)
#pragma unroll
                for (int j = 0; j < 8; j++) acc[i][j] += ar[i] * br[j];
        }
    }

#pragma unroll
    for (int i = 0; i < 8; i++)
#pragma unroll
        for (int j = 0; j < 8; j += 4) {
            float4 o4 = make_float4(acc[i][j], acc[i][j + 1], acc[i][j + 2], acc[i][j + 3]);
            *(float4*)&g_d[(size_t)(bm + tr + i) * N + bn + tc + j] = o4;
        }
}

// ---------------------------------------------------------------------------
// prep: inv_norm from diag(d), zero per-step counters
// ---------------------------------------------------------------------------
__global__ void prep_kernel()
{
    int idx = blockIdx.x * blockDim.x + threadIdx.x;
    if (idx < O_) g_inv[idx] = 1.0f / (g_d[(size_t)idx * O_ + idx] + EPSV);
    if (idx < T_) g_cnt[idx] = 0;
}

// ---------------------------------------------------------------------------
// Scan v2: one CTA per batch, 1024 threads, one neuron per thread.
// ---------------------------------------------------------------------------
__global__ void __launch_bounds__(1024) scan_kernel(
    const float* __restrict__ V,
    const float* __restrict__ bb,
    const float* __restrict__ beta_p,
    float* __restrict__ out)
{
    const int b = blockIdx.x;
    const int o = threadIdx.x;
    const float beta = beta_p[0];
    const float ombeta = 1.0f - beta;

    __shared__ int act[2][O_];
    __shared__ int nact[2];
    __shared__ int scnt;

    if (o < 2) nact[o] = 0;
    if (o == 0) scnt = 0;

    float mem = 0.f;
    const float inv = g_inv[o];
    const float bo  = bb[o];
    const float* hrow = g_h + (size_t)b * T_ * O_ + o;
    float*       orow = out + (size_t)b * T_ * O_ + o;

    float h_next = hrow[0];
    __syncthreads();

    int cur = 0;
    for (int t = 0; t < T_; t++) {
        const float h_cur = h_next;
        if (t + 1 < T_) h_next = hrow[(size_t)(t + 1) * O_];

        const int na = nact[cur];
        float rst = 0.f, rec = 0.f;
        for (int a = 0; a < na; a++) {
            const int i = act[cur][a];
            rst += g_d[(size_t)i * O_ + o];
            rec += V[(size_t)i * O_ + o];
        }

        mem = (mem - rst) * beta + (h_cur + rec) * ombeta;
        const float mthr = mem * inv - bo;
        const float s = (mthr > 0.f) ? 1.0f : 0.0f;
        orow[(size_t)t * O_] = s;
        if (s != 0.f) {
            const int p = atomicAdd(&nact[cur ^ 1], 1);
            act[cur ^ 1][p] = o;
            atomicAdd(&scnt, 1);
        }
        __syncthreads();
        if (o == 0) {
            if (scnt) { atomicAdd(&g_cnt[t], scnt); scnt = 0; }
            nact[cur] = 0;
        }
        cur ^= 1;
        __syncthreads();
    }
}

// ---------------------------------------------------------------------------
// finalize: loss and spike-spread scalars
// ---------------------------------------------------------------------------
__global__ void finalize_kernel(float* __restrict__ out, int out_size)
{
    __shared__ int s_tot[128];
    __shared__ int s_max[128];
    const int tid = threadIdx.x;
    int tot = 0, mx = 0;
    for (int t = tid; t < T_; t += 128) {
        int c = g_cnt[t];
        tot += c;
        mx = (c > mx) ? c : mx;
    }
    s_tot[tid] = tot; s_max[tid] = mx;
    __syncthreads();
    for (int s = 64; s > 0; s >>= 1) {
        if (tid < s) {
            s_tot[tid] += s_tot[tid + s];
            s_max[tid] = (s_max[tid + s] > s_max[tid]) ? s_max[tid + s] : s_max[tid];
        }
        __syncthreads();
    }
    if (tid == 0) {
        const size_t base = (size_t)B_ * T_ * O_;
        if ((size_t)out_size >= base + 2) {
            out[base]     = 0.5f * (float)s_tot[0] / (float)((size_t)B_ * T_ * O_);
            out[base + 1] = (float)s_max[0] / (float)(B_ * O_);
        }
    }
}

// ---------------------------------------------------------------------------
extern "C" void kernel_launch(void* const* d_in, const int* in_sizes, int n_in,
                              void* d_out, int out_size)
{
    const float* x    = (const float*)d_in[0];   // [B,T,I]
    const float* w    = (const float*)d_in[1];   // [I,O]
    const float* v    = (const float*)d_in[2];   // [O,O]
    const float* beta = (const float*)d_in[3];   // [1]
    const float* bb   = (const float*)d_in[4];   // [O]
    float* out = (float*)d_out;

    cudaFuncSetAttribute(gemm_h_mma, cudaFuncAttributeMaxDynamicSharedMemorySize,
                         GH_SMEM_BYTES);

    // 0) tf32 splits (globals referenced in device code only)
    split_x_kernel<<<2048, 256>>>(x);
    split_w_kernel<<<256, 256>>>(w);

    // 1) h = x @ w via mma.sync tf32 (3xTF32), 4-stage cp.async
    gemm_h_mma<<<dim3(O_ / 128, (B_ * T_) / 128), 512, GH_SMEM_BYTES>>>();

    // 2) d = w^T w (SIMT)
    gemm_d<<<dim3(O_ / 128, O_ / 128), 256>>>(w);

    // 3) inv_norm + zero counters
    prep_kernel<<<4, 256>>>();

    // 4) per-batch recurrent scan
    scan_kernel<<<B_, 1024>>>(v, bb, beta, out);

    // 5) scalar losses
    finalize_kernel<<<1, 128>>>(out, out_size);
}

// round 14
// speedup vs baseline: 3.7266x; 1.7141x over previous
#include <cuda_runtime.h>
#include <cuda_fp16.h>
#include <cstdint>

// Problem constants
#define B_ 128
#define T_ 100
#define I_ 1024
#define O_ 1024
#define EPSV 1e-8f
#define LO_SCALE 2048.0f        // 2^11
#define LO_INV   (1.0f / 2048.0f)

// Scratch (__device__ globals; referenced ONLY in device code — R6 lesson)
__device__ __align__(16) float  g_h[(size_t)B_ * T_ * O_];     // h = x@w
__device__ __align__(16) float  g_d[(size_t)O_ * O_];          // d = w^T w
__device__ __align__(16) float  g_inv[O_];                     // 1/(norm+eps)
__device__ int    g_cnt[T_];                                   // per-step spike counts
__device__ __align__(16) __half g_xh16[(size_t)B_ * T_ * I_];  // x hi fp16
__device__ __align__(16) __half g_xl16[(size_t)B_ * T_ * I_];  // (x-hi)*2^11 fp16
__device__ __align__(16) __half g_wTh16[(size_t)O_ * I_];      // w^T hi, [o][a]
__device__ __align__(16) __half g_wTl16[(size_t)O_ * I_];      // w^T lo*2^11

// ---------------------------------------------------------------------------
// helpers (plain sm_80-class PTX — harness targets sm_103 w/o 'a')
// ---------------------------------------------------------------------------
__device__ __forceinline__ uint32_t smem_u32(const void* p) {
    uint32_t a;
    asm("{ .reg .u64 t; cvta.to.shared.u64 t, %1; cvt.u32.u64 %0, t; }" : "=r"(a) : "l"(p));
    return a;
}
__device__ __forceinline__ void cp16(uint32_t dst, const void* src) {
    asm volatile("cp.async.cg.shared.global [%0], [%1], 16;" :: "r"(dst), "l"(src));
}
#define CP_COMMIT() asm volatile("cp.async.commit_group;" ::: "memory")
#define CP_WAIT(n)  asm volatile("cp.async.wait_group %0;" :: "n"(n) : "memory")

__device__ __forceinline__ void mma_f16(float c[4], const uint32_t a[4],
                                        const uint32_t b[2]) {
    asm volatile(
        "mma.sync.aligned.m16n8k16.row.col.f32.f16.f16.f32 "
        "{%0,%1,%2,%3}, {%4,%5,%6,%7}, {%8,%9}, {%0,%1,%2,%3};"
        : "+f"(c[0]), "+f"(c[1]), "+f"(c[2]), "+f"(c[3])
        : "r"(a[0]), "r"(a[1]), "r"(a[2]), "r"(a[3]), "r"(b[0]), "r"(b[1]));
}

__device__ __forceinline__ void split16(float v, __half& hi, __half& lo) {
    hi = __float2half_rn(v);
    lo = __float2half_rn((v - __half2float(hi)) * LO_SCALE);
}

// ---------------------------------------------------------------------------
// split_x_f16: x -> (g_xh16, g_xl16), elementwise
// ---------------------------------------------------------------------------
__global__ void split_x_f16(const float* __restrict__ src)
{
    const int n4 = (B_ * T_ * I_) / 4;
    const float4* s4 = (const float4*)src;
    uint2* h2 = (uint2*)g_xh16;    // 4 halves per uint2
    uint2* l2 = (uint2*)g_xl16;
    for (int i = blockIdx.x * blockDim.x + threadIdx.x; i < n4;
         i += gridDim.x * blockDim.x) {
        float4 v = s4[i];
        __half h0, h1, h2v, h3, l0, l1, l2v, l3;
        split16(v.x, h0, l0); split16(v.y, h1, l1);
        split16(v.z, h2v, l2v); split16(v.w, h3, l3);
        uint2 ho, lo_;
        ho.x = (uint32_t)__half_as_ushort(h0) | ((uint32_t)__half_as_ushort(h1) << 16);
        ho.y = (uint32_t)__half_as_ushort(h2v) | ((uint32_t)__half_as_ushort(h3) << 16);
        lo_.x = (uint32_t)__half_as_ushort(l0) | ((uint32_t)__half_as_ushort(l1) << 16);
        lo_.y = (uint32_t)__half_as_ushort(l2v) | ((uint32_t)__half_as_ushort(l3) << 16);
        h2[i] = ho; l2[i] = lo_;
    }
}

// ---------------------------------------------------------------------------
// split_wT_f16: w[a][o] -> wT hi/lo fp16 [o][a] (32x32 smem transpose)
// ---------------------------------------------------------------------------
__global__ void split_wT_f16(const float* __restrict__ w)
{
    __shared__ float tile[32][33];
    const int bx = blockIdx.x * 32;   // o
    const int by = blockIdx.y * 32;   // a
    const int tx = threadIdx.x, ty = threadIdx.y;
#pragma unroll
    for (int j = 0; j < 4; j++)
        tile[ty + j * 8][tx] = w[(size_t)(by + ty + j * 8) * O_ + bx + tx];
    __syncthreads();
#pragma unroll
    for (int j = 0; j < 4; j++) {
        float v = tile[tx][ty + j * 8];        // w[a=by+tx][o=bx+ty+j*8]
        __half hi, lo;
        split16(v, hi, lo);
        size_t dst = (size_t)(bx + ty + j * 8) * I_ + by + tx;
        g_wTh16[dst] = hi;
        g_wTl16[dst] = lo;
    }
}

// ---------------------------------------------------------------------------
// gemm_fused: fp16 3-term mma (m16n8k16).
//   y < 100 : g_h[M=12800,N=1024] = x * w        (A = x-split)
//   y >= 100: g_d[1024,1024]      = w^T w        (A = wT-split)
// B is always the wT-split ([n][k], k-contiguous).
// CTA 128x128, 512 threads, 16 warps (4m x 4n), BK=16, 4-stage cp.async.
// SMEM rows: 16 halves (8 half2 words) padded to 12 words -> banks 12g+t4
// all-distinct mod 32 for consumer loads.
// ---------------------------------------------------------------------------
#define SROW  12                    // words per tile row
#define TILEW (128 * SROW)          // 1536 words per tile
#define AHW 0
#define ALW TILEW
#define BHW (2 * TILEW)
#define BLW (3 * TILEW)
#define STGW (4 * TILEW)            // 6144 words = 24KB per stage
#define GF_SMEM_BYTES (4 * STGW * 4)  // 98304 B

__global__ void __launch_bounds__(512) gemm_fused()
{
    extern __shared__ uint32_t smw[];
    const uint32_t sbase = smem_u32(smw);
    const int tid  = threadIdx.x;
    const int wid  = tid >> 5;
    const int lane = tid & 31;
    const int g    = lane >> 2;
    const int t4   = lane & 3;
    const bool is_h = (blockIdx.y < 100);
    const int bm   = (is_h ? blockIdx.y : (blockIdx.y - 100)) * 128;
    const int bn   = blockIdx.x * 128;
    const int wm   = (wid >> 2) * 32;
    const int wn   = (wid & 3) * 32;

    // producer: r = row 0..127, sub: 0/1 -> hi blk0/blk1, 2/3 -> lo blk0/blk1
    const int pr   = tid >> 2;
    const int sub  = tid & 3;
    const int blk  = sub & 1;                 // 16-byte block within row
    const bool hiP = (sub < 2);

    const __half* srcA = (is_h ? (hiP ? g_xh16 : g_xl16)
                               : (hiP ? g_wTh16 : g_wTl16))
                         + (size_t)(bm + pr) * I_ + blk * 8;
    const __half* srcB = (hiP ? g_wTh16 : g_wTl16)
                         + (size_t)(bn + pr) * I_ + blk * 8;
    const uint32_t dstA = sbase + ((hiP ? AHW : ALW) + pr * SROW + blk * 4) * 4;
    const uint32_t dstB = sbase + ((hiP ? BHW : BLW) + pr * SROW + blk * 4) * 4;

    float acch[2][4][4], accm[2][4][4];
#pragma unroll
    for (int i = 0; i < 2; i++)
#pragma unroll
        for (int j = 0; j < 4; j++)
#pragma unroll
            for (int q = 0; q < 4; q++) { acch[i][j][q] = 0.f; accm[i][j][q] = 0.f; }

    auto fill = [&](int stage, int chunk) {
        const uint32_t so = stage * (STGW * 4);
        const int k0 = chunk * 16;
        cp16(dstA + so, srcA + k0);
        cp16(dstB + so, srcB + k0);
        CP_COMMIT();
    };

    auto compute = [&](int stage) {
        const uint32_t* base = smw + stage * STGW;
        const uint32_t* Ah = base + AHW;
        const uint32_t* Al = base + ALW;
        const uint32_t* Bh = base + BHW;
        const uint32_t* Bl = base + BLW;
        uint32_t ah[2][4], al[2][4], bh[4][2], bl[4][2];
#pragma unroll
        for (int mt = 0; mt < 2; mt++) {
            const int r0 = (wm + mt * 16 + g) * SROW;
            const int r1 = r0 + 8 * SROW;
            ah[mt][0] = Ah[r0 + t4];     ah[mt][1] = Ah[r1 + t4];
            ah[mt][2] = Ah[r0 + t4 + 4]; ah[mt][3] = Ah[r1 + t4 + 4];
            al[mt][0] = Al[r0 + t4];     al[mt][1] = Al[r1 + t4];
            al[mt][2] = Al[r0 + t4 + 4]; al[mt][3] = Al[r1 + t4 + 4];
        }
#pragma unroll
        for (int nt = 0; nt < 4; nt++) {
            const int c0 = (wn + nt * 8 + g) * SROW;
            bh[nt][0] = Bh[c0 + t4]; bh[nt][1] = Bh[c0 + t4 + 4];
            bl[nt][0] = Bl[c0 + t4]; bl[nt][1] = Bl[c0 + t4 + 4];
        }
#pragma unroll
        for (int mt = 0; mt < 2; mt++)
#pragma unroll
            for (int nt = 0; nt < 4; nt++) {
                mma_f16(acch[mt][nt], ah[mt], bh[nt]);
                mma_f16(accm[mt][nt], ah[mt], bl[nt]);
                mma_f16(accm[mt][nt], al[mt], bh[nt]);
            }
    };

    fill(0, 0);
    fill(1, 1);
    fill(2, 2);

    for (int c = 0; c < 64; c++) {
        CP_WAIT(2);                 // chunk c resident (3 groups in flight)
        __syncthreads();
        compute(c & 3);
        if (c + 3 < 64) fill((c + 3) & 3, c + 3);
        else CP_COMMIT();           // keep wait-count invariant
    }

    // epilogue: h = acc_hi + acc_mid * 2^-11
    float* dst = is_h ? g_h : g_d;
#pragma unroll
    for (int mt = 0; mt < 2; mt++)
#pragma unroll
        for (int nt = 0; nt < 4; nt++) {
            const int row0 = bm + wm + mt * 16 + g;
            const int col  = bn + wn + nt * 8 + t4 * 2;
            float* a = acch[mt][nt];
            float* m = accm[mt][nt];
            *(float2*)&dst[(size_t)row0 * O_ + col] =
                make_float2(a[0] + m[0] * LO_INV, a[1] + m[1] * LO_INV);
            *(float2*)&dst[(size_t)(row0 + 8) * O_ + col] =
                make_float2(a[2] + m[2] * LO_INV, a[3] + m[3] * LO_INV);
        }
}

// ---------------------------------------------------------------------------
// prep: inv_norm from diag(d), zero per-step counters
// ---------------------------------------------------------------------------
__global__ void prep_kernel()
{
    int idx = blockIdx.x * blockDim.x + threadIdx.x;
    if (idx < O_) g_inv[idx] = 1.0f / (g_d[(size_t)idx * O_ + idx] + EPSV);
    if (idx < T_) g_cnt[idx] = 0;
}

// ---------------------------------------------------------------------------
// Scan: one CTA per batch, 1024 threads, one neuron per thread; sparse-exact.
// ---------------------------------------------------------------------------
__global__ void __launch_bounds__(1024) scan_kernel(
    const float* __restrict__ V,
    const float* __restrict__ bb,
    const float* __restrict__ beta_p,
    float* __restrict__ out)
{
    const int b = blockIdx.x;
    const int o = threadIdx.x;
    const float beta = beta_p[0];
    const float ombeta = 1.0f - beta;

    __shared__ int act[2][O_];
    __shared__ int nact[2];
    __shared__ int scnt;

    if (o < 2) nact[o] = 0;
    if (o == 0) scnt = 0;

    float mem = 0.f;
    const float inv = g_inv[o];
    const float bo  = bb[o];
    const float* hrow = g_h + (size_t)b * T_ * O_ + o;
    float*       orow = out + (size_t)b * T_ * O_ + o;

    float h_next = hrow[0];
    __syncthreads();

    int cur = 0;
    for (int t = 0; t < T_; t++) {
        const float h_cur = h_next;
        if (t + 1 < T_) h_next = hrow[(size_t)(t + 1) * O_];

        const int na = nact[cur];
        float rst = 0.f, rec = 0.f;
        for (int a = 0; a < na; a++) {
            const int i = act[cur][a];
            rst += g_d[(size_t)i * O_ + o];
            rec += V[(size_t)i * O_ + o];
        }

        mem = (mem - rst) * beta + (h_cur + rec) * ombeta;
        const float mthr = mem * inv - bo;
        const float s = (mthr > 0.f) ? 1.0f : 0.0f;
        orow[(size_t)t * O_] = s;
        if (s != 0.f) {
            const int p = atomicAdd(&nact[cur ^ 1], 1);
            act[cur ^ 1][p] = o;
            atomicAdd(&scnt, 1);
        }
        __syncthreads();
        if (o == 0) {
            if (scnt) { atomicAdd(&g_cnt[t], scnt); scnt = 0; }
            nact[cur] = 0;
        }
        cur ^= 1;
        __syncthreads();
    }
}

// ---------------------------------------------------------------------------
// finalize: loss and spike-spread scalars
// ---------------------------------------------------------------------------
__global__ void finalize_kernel(float* __restrict__ out, int out_size)
{
    __shared__ int s_tot[128];
    __shared__ int s_max[128];
    const int tid = threadIdx.x;
    int tot = 0, mx = 0;
    for (int t = tid; t < T_; t += 128) {
        int c = g_cnt[t];
        tot += c;
        mx = (c > mx) ? c : mx;
    }
    s_tot[tid] = tot; s_max[tid] = mx;
    __syncthreads();
    for (int s = 64; s > 0; s >>= 1) {
        if (tid < s) {
            s_tot[tid] += s_tot[tid + s];
            s_max[tid] = (s_max[tid + s] > s_max[tid]) ? s_max[tid + s] : s_max[tid];
        }
        __syncthreads();
    }
    if (tid == 0) {
        const size_t base = (size_t)B_ * T_ * O_;
        if ((size_t)out_size >= base + 2) {
            out[base]     = 0.5f * (float)s_tot[0] / (float)((size_t)B_ * T_ * O_);
            out[base + 1] = (float)s_max[0] / (float)(B_ * O_);
        }
    }
}

// ---------------------------------------------------------------------------
extern "C" void kernel_launch(void* const* d_in, const int* in_sizes, int n_in,
                              void* d_out, int out_size)
{
    const float* x    = (const float*)d_in[0];   // [B,T,I]
    const float* w    = (const float*)d_in[1];   // [I,O]
    const float* v    = (const float*)d_in[2];   // [O,O]
    const float* beta = (const float*)d_in[3];   // [1]
    const float* bb   = (const float*)d_in[4];   // [O]
    float* out = (float*)d_out;

    cudaFuncSetAttribute(gemm_fused, cudaFuncAttributeMaxDynamicSharedMemorySize,
                         GF_SMEM_BYTES);

    // 0) fp16 hi/lo splits (x elementwise; w transposed)
    split_x_f16<<<2048, 256>>>(x);
    split_wT_f16<<<dim3(32, 32), dim3(32, 8)>>>(w);

    // 1) fused: h = x@w (y<100) and d = w^T w (y>=100), fp16 3-term mma
    gemm_fused<<<dim3(O_ / 128, 100 + O_ / 128), 512, GF_SMEM_BYTES>>>();

    // 2) inv_norm + zero counters
    prep_kernel<<<4, 256>>>();

    // 3) per-batch recurrent scan
    scan_kernel<<<B_, 1024>>>(v, bb, beta, out);

    // 4) scalar losses
    finalize_kernel<<<1, 128>>>(out, out_size);
}